// round 5
// baseline (speedup 1.0000x reference)
#include <cuda_runtime.h>
#include <cuda_bf16.h>

#define N_USER 100000
#define N_ITEM 50000
#define NTOT   150000
#define EMB    64
#define FEAT   384
#define NNZ    2400000
#define EPS_F  1e-8f

// ---------------- device scratch (static, no allocations) ----------------
__device__ float          g_ego[NTOT * EMB];       // 38.4 MB fp32
__device__ __nv_bfloat162 g_ego16[NTOT * 32];      // 19.2 MB bf16
__device__ __nv_bfloat162 g_x1[NTOT * 32];
__device__ __nv_bfloat162 g_x2[NTOT * 32];
__device__ __nv_bfloat162 g_x3[NTOT * 32];
__device__ float g_norm[NTOT];
__device__ int   g_counts[NTOT];
__device__ int   g_cursor[NTOT];
__device__ int2  g_seg[NTOT];                      // (start, end) per row
__device__ int2  g_edges[NNZ];                     // (col, val-bits)
__device__ int   g_acur;                           // global segment cursor

// ---------------- 1: ego users + zero scratch ----------------
__global__ void k_ego_user(const float* __restrict__ user,
                           const float* __restrict__ prompt)
{
    __shared__ float ps[EMB];
    int tid = threadIdx.x;
    if (tid < EMB) {
        float s = 0.f;
#pragma unroll
        for (int p = 0; p < 8; p++) s += prompt[p * EMB + tid];
        ps[tid] = s;
    }
    __syncthreads();
    int gtid = blockIdx.x * blockDim.x + tid;
    // fused scratch zeroing (3.2M threads >> NTOT)
    if (gtid < NTOT) g_counts[gtid] = 0;
    if (gtid == 0)   g_acur = 0;

    int warp = gtid >> 5;
    int lane = tid & 31;
    if (warp >= N_USER) return;
    float2 u = ((const float2*)user)[warp * 32 + lane];
    float2 p2 = *(const float2*)&ps[lane * 2];
    float vx = u.x + p2.x, vy = u.y + p2.y;
    ((float2*)g_ego)[warp * 32 + lane] = make_float2(vx, vy);
    g_ego16[warp * 32 + lane] = __floats2bfloat162_rn(vx, vy);
    float s = vx * vx + vy * vy;
#pragma unroll
    for (int o = 16; o; o >>= 1) s += __shfl_xor_sync(0xffffffffu, s, o);
    if (lane == 0) g_norm[warp] = sqrtf(s);
}

// ---------------- 2: item GEMM (R2-proven) + fused tanh/norm/bf16 ---------
__global__ __launch_bounds__(256) void k_item(const float* __restrict__ fea,
                                              const float* __restrict__ w,
                                              const float* __restrict__ b)
{
    __shared__ float sf[128][33];
    __shared__ float sw[32][64];
    int tid = threadIdx.x;
    int row0 = blockIdx.x * 128;
    int ty = tid >> 4;      // 0..15 -> rows ty*8..+7
    int tx = tid & 15;      // cols tx*4..+3

    float acc[8][4];
#pragma unroll
    for (int r = 0; r < 8; r++)
#pragma unroll
        for (int c = 0; c < 4; c++) acc[r][c] = 0.f;

    for (int k0 = 0; k0 < FEAT; k0 += 32) {
#pragma unroll
        for (int i = 0; i < 16; i++) {
            int l = tid + i * 256;
            int r = l >> 5, kk = l & 31;
            int gr = row0 + r;
            sf[r][kk] = (gr < N_ITEM) ? fea[gr * FEAT + k0 + kk] : 0.f;
        }
#pragma unroll
        for (int i = 0; i < 8; i++) {
            int l = tid + i * 256;
            int kk = l >> 6, c = l & 63;
            sw[kk][c] = w[(k0 + kk) * EMB + c];
        }
        __syncthreads();
#pragma unroll
        for (int kk = 0; kk < 32; kk++) {
            float4 wv = *(const float4*)&sw[kk][tx * 4];
#pragma unroll
            for (int r = 0; r < 8; r++) {
                float f = sf[ty * 8 + r][kk];
                acc[r][0] += f * wv.x;
                acc[r][1] += f * wv.y;
                acc[r][2] += f * wv.z;
                acc[r][3] += f * wv.w;
            }
        }
        __syncthreads();
    }

#pragma unroll
    for (int r = 0; r < 8; r++) {
        int gr = row0 + ty * 8 + r;
        float c0 = tanhf(acc[r][0] + b[tx * 4 + 0]);
        float c1 = tanhf(acc[r][1] + b[tx * 4 + 1]);
        float c2 = tanhf(acc[r][2] + b[tx * 4 + 2]);
        float c3 = tanhf(acc[r][3] + b[tx * 4 + 3]);
        float s = c0 * c0 + c1 * c1 + c2 * c2 + c3 * c3;
#pragma unroll
        for (int o = 1; o < 16; o <<= 1) s += __shfl_xor_sync(0xffffffffu, s, o);
        if (gr < N_ITEM) {
            int row = N_USER + gr;
            *(float4*)&g_ego[row * EMB + tx * 4] = make_float4(c0, c1, c2, c3);
            g_ego16[row * 32 + tx * 2 + 0] = __floats2bfloat162_rn(c0, c1);
            g_ego16[row * 32 + tx * 2 + 1] = __floats2bfloat162_rn(c2, c3);
            if (tx == 0) g_norm[row] = sqrtf(s);
        }
    }
}

// ---------------- 3: histogram (int4 loads) ----------------
__global__ void k_hist(const int* __restrict__ rows)
{
    int stride = gridDim.x * blockDim.x;
    const int4* r4 = (const int4*)rows;
    for (int e = blockIdx.x * blockDim.x + threadIdx.x; e < NNZ / 4; e += stride) {
        int4 v = __ldg(&r4[e]);
        atomicAdd(&g_counts[v.x], 1);
        atomicAdd(&g_counts[v.y], 1);
        atomicAdd(&g_counts[v.z], 1);
        atomicAdd(&g_counts[v.w], 1);
    }
}

// ---------------- 4: segment allocation (replaces 3-kernel scan) ----------
__global__ void k_alloc()
{
    int row  = blockIdx.x * blockDim.x + threadIdx.x;
    int lane = threadIdx.x & 31;
    int cnt = (row < NTOT) ? g_counts[row] : 0;
    int pre = cnt;
#pragma unroll
    for (int o = 1; o < 32; o <<= 1) {
        int t = __shfl_up_sync(0xffffffffu, pre, o);
        if (lane >= o) pre += t;
    }
    int excl  = pre - cnt;
    int total = __shfl_sync(0xffffffffu, pre, 31);
    int base = 0;
    if (lane == 0) base = atomicAdd(&g_acur, total);
    base = __shfl_sync(0xffffffffu, base, 0);
    if (row < NTOT) {
        int s = base + excl;
        g_seg[row]    = make_int2(s, s + cnt);
        g_cursor[row] = 0;
    }
}

// ---------------- 5: scatter ----------------
__global__ void k_scatter(const int* __restrict__ rows,
                          const int* __restrict__ cols,
                          const float* __restrict__ vals)
{
    int stride = gridDim.x * blockDim.x;
    for (int e = blockIdx.x * blockDim.x + threadIdx.x; e < NNZ; e += stride) {
        int r = rows[e];
        int p = g_seg[r].x + atomicAdd(&g_cursor[r], 1);
        g_edges[p] = make_int2(cols[e], __float_as_int(vals[e]));
    }
}

// ---------------- 6-8: fused SpMM + cosine-reweight (bf16) ----------------
__global__ __launch_bounds__(256) void k_layerA(const __nv_bfloat162* __restrict__ xin,
                                                __nv_bfloat162* __restrict__ xout)
{
    int warp = (blockIdx.x * blockDim.x + threadIdx.x) >> 5;
    int lane = threadIdx.x & 31;
    if (warp >= NTOT) return;

    int2 seg = __ldg(&g_seg[warp]);

    float a0 = 0.f, a1 = 0.f;
#pragma unroll 8
    for (int p = seg.x; p < seg.y; p++) {
        int2 ed = __ldg(&g_edges[p]);
        float v = __int_as_float(ed.y);
        float2 f = __bfloat1622float2(__ldg(&xin[ed.x * 32 + lane]));
        a0 += v * f.x;
        a1 += v * f.y;
    }

    float2 ev = __bfloat1622float2(g_ego16[warp * 32 + lane]);
    float dot = a0 * ev.x + a1 * ev.y;
    float nn  = a0 * a0 + a1 * a1;
#pragma unroll
    for (int o = 16; o; o >>= 1) {
        dot += __shfl_xor_sync(0xffffffffu, dot, o);
        nn  += __shfl_xor_sync(0xffffffffu, nn,  o);
    }
    float wgt = dot / fmaxf(sqrtf(nn) * g_norm[warp], EPS_F);

    xout[warp * 32 + lane] = __floats2bfloat162_rn(wgt * a0, wgt * a1);
}

// ---------------- 9: final layer + fused total sum ----------------
__global__ __launch_bounds__(256) void k_layerB(float* __restrict__ out)
{
    int warp = (blockIdx.x * blockDim.x + threadIdx.x) >> 5;
    int lane = threadIdx.x & 31;
    if (warp >= NTOT) return;

    int2 seg = __ldg(&g_seg[warp]);

    float a0 = 0.f, a1 = 0.f;
#pragma unroll 8
    for (int p = seg.x; p < seg.y; p++) {
        int2 ed = __ldg(&g_edges[p]);
        float v = __int_as_float(ed.y);
        float2 f = __bfloat1622float2(__ldg(&g_x3[ed.x * 32 + lane]));
        a0 += v * f.x;
        a1 += v * f.y;
    }

    int idx = warp * 32 + lane;
    float2 ev = ((const float2*)g_ego)[idx];
    float dot = a0 * ev.x + a1 * ev.y;
    float nn  = a0 * a0 + a1 * a1;
#pragma unroll
    for (int o = 16; o; o >>= 1) {
        dot += __shfl_xor_sync(0xffffffffu, dot, o);
        nn  += __shfl_xor_sync(0xffffffffu, nn,  o);
    }
    float wgt = dot / fmaxf(sqrtf(nn) * g_norm[warp], EPS_F);

    float2 v1 = __bfloat1622float2(g_x1[idx]);
    float2 v2 = __bfloat1622float2(g_x2[idx]);
    float2 v3 = __bfloat1622float2(g_x3[idx]);
    float2 r;
    r.x = ev.x + v1.x + v2.x + v3.x + wgt * a0;
    r.y = ev.y + v1.y + v2.y + v3.y + wgt * a1;
    ((float2*)out)[idx] = r;
}

// ---------------- launch (single stream, 9 kernels) ----------------
extern "C" void kernel_launch(void* const* d_in, const int* in_sizes, int n_in,
                              void* d_out, int out_size)
{
    const float* user   = (const float*)d_in[0];
    const float* item   = (const float*)d_in[1];
    const float* prompt = (const float*)d_in[2];
    const float* mw     = (const float*)d_in[3];
    const float* mb     = (const float*)d_in[4];
    const int*   rows   = (const int*)d_in[5];
    const int*   cols   = (const int*)d_in[6];
    const float* vals   = (const float*)d_in[7];
    float* out = (float*)d_out;

    void *p16, *p1, *p2, *p3;
    cudaGetSymbolAddress(&p16, g_ego16);
    cudaGetSymbolAddress(&p1,  g_x1);
    cudaGetSymbolAddress(&p2,  g_x2);
    cudaGetSymbolAddress(&p3,  g_x3);
    __nv_bfloat162* ego16 = (__nv_bfloat162*)p16;
    __nv_bfloat162* x1    = (__nv_bfloat162*)p1;
    __nv_bfloat162* x2    = (__nv_bfloat162*)p2;
    __nv_bfloat162* x3    = (__nv_bfloat162*)p3;

    const int LB = (NTOT * 32 + 255) / 256;

    // 1-2: ego construction (also zeroes CSR scratch)
    k_ego_user<<<(N_USER * 32 + 255) / 256, 256>>>(user, prompt);
    k_item    <<<(N_ITEM + 127) / 128, 256>>>(item, mw, mb);

    // 3-5: CSR build
    k_hist   <<<2048, 256>>>(rows);
    k_alloc  <<<(NTOT + 255) / 256, 256>>>();
    k_scatter<<<2048, 256>>>(rows, cols, vals);

    // 6-9: propagation layers  (launch #6 = k_layerA -> ncu target)
    k_layerA<<<LB, 256>>>(ego16, x1);
    k_layerA<<<LB, 256>>>(x1,    x2);
    k_layerA<<<LB, 256>>>(x2,    x3);
    k_layerB<<<LB, 256>>>(out);
}

// round 6
// speedup vs baseline: 1.8240x; 1.8240x over previous
#include <cuda_runtime.h>
#include <cuda_bf16.h>

#define N_USER 100000
#define N_ITEM 50000
#define NTOT   150000
#define EMB    64
#define FEAT   384
#define NNZ    2400000
#define EPS_F  1e-8f

// ---------------- device scratch (static, no allocations) ----------------
__device__ float          g_ego[NTOT * EMB];       // 38.4 MB fp32
__device__ __nv_bfloat162 g_ego16[NTOT * 32];      // 19.2 MB bf16
__device__ __nv_bfloat162 g_x1[NTOT * 32];
__device__ __nv_bfloat162 g_x2[NTOT * 32];
__device__ __nv_bfloat162 g_x3[NTOT * 32];
__device__ float g_norm[NTOT];
__device__ int   g_counts[NTOT];
__device__ int   g_cursor[NTOT];
__device__ int   g_rowptr[NTOT + 1];
__device__ int2  g_edges[NNZ];
__device__ int   g_bsum[256];

// ---------------- CSR build (R2/R4 proven path — DO NOT TOUCH) ----------------
__global__ void k_zero()
{
    int i = blockIdx.x * blockDim.x + threadIdx.x;
    if (i < NTOT) { g_counts[i] = 0; g_cursor[i] = 0; }
}

__global__ void k_hist(const int* __restrict__ rows)
{
    int stride = gridDim.x * blockDim.x;
    for (int e = blockIdx.x * blockDim.x + threadIdx.x; e < NNZ; e += stride)
        atomicAdd(&g_counts[rows[e]], 1);
}

__global__ void k_scan1()
{
    __shared__ int sh[1024];
    int tid = threadIdx.x;
    int gid = blockIdx.x * 1024 + tid;
    int v = (gid < NTOT) ? g_counts[gid] : 0;
    sh[tid] = v;
    __syncthreads();
    for (int o = 1; o < 1024; o <<= 1) {
        int t = (tid >= o) ? sh[tid - o] : 0;
        __syncthreads();
        if (tid >= o) sh[tid] += t;
        __syncthreads();
    }
    if (gid < NTOT) g_rowptr[gid] = sh[tid] - v;
    if (tid == 1023) g_bsum[blockIdx.x] = sh[1023];
}

__global__ void k_scan2(int nb)
{
    __shared__ int sh[256];
    int tid = threadIdx.x;
    int v = (tid < nb) ? g_bsum[tid] : 0;
    sh[tid] = v;
    __syncthreads();
    for (int o = 1; o < 256; o <<= 1) {
        int t = (tid >= o) ? sh[tid - o] : 0;
        __syncthreads();
        if (tid >= o) sh[tid] += t;
        __syncthreads();
    }
    g_bsum[tid] = sh[tid] - v;
}

__global__ void k_scan3()
{
    int gid = blockIdx.x * 1024 + threadIdx.x;
    if (gid < NTOT) g_rowptr[gid] += g_bsum[blockIdx.x];
    if (gid == 0) g_rowptr[NTOT] = NNZ;
}

__global__ void k_scatter(const int* __restrict__ rows,
                          const int* __restrict__ cols,
                          const float* __restrict__ vals)
{
    int stride = gridDim.x * blockDim.x;
    for (int e = blockIdx.x * blockDim.x + threadIdx.x; e < NNZ; e += stride) {
        int r = rows[e];
        int p = g_rowptr[r] + atomicAdd(&g_cursor[r], 1);
        g_edges[p] = make_int2(cols[e], __float_as_int(vals[e]));
    }
}

// ---------------- ego construction (fused norm + bf16) ----------------
__global__ void k_ego_user(const float* __restrict__ user,
                           const float* __restrict__ prompt)
{
    __shared__ float ps[EMB];
    int tid = threadIdx.x;
    if (tid < EMB) {
        float s = 0.f;
#pragma unroll
        for (int p = 0; p < 8; p++) s += prompt[p * EMB + tid];
        ps[tid] = s;
    }
    __syncthreads();
    int warp = (blockIdx.x * blockDim.x + tid) >> 5;
    int lane = tid & 31;
    if (warp >= N_USER) return;
    float2 u = ((const float2*)user)[warp * 32 + lane];
    float2 p2 = *(const float2*)&ps[lane * 2];
    float vx = u.x + p2.x, vy = u.y + p2.y;
    ((float2*)g_ego)[warp * 32 + lane] = make_float2(vx, vy);
    g_ego16[warp * 32 + lane] = __floats2bfloat162_rn(vx, vy);
    float s = vx * vx + vy * vy;
#pragma unroll
    for (int o = 16; o; o >>= 1) s += __shfl_xor_sync(0xffffffffu, s, o);
    if (lane == 0) g_norm[warp] = sqrtf(s);
}

// R2-proven tiled SGEMM + fused tanh/norm/bf16 epilogue (R4 state)
__global__ __launch_bounds__(256) void k_item(const float* __restrict__ fea,
                                              const float* __restrict__ w,
                                              const float* __restrict__ b)
{
    __shared__ float sf[128][33];
    __shared__ float sw[32][64];
    int tid = threadIdx.x;
    int row0 = blockIdx.x * 128;
    int ty = tid >> 4;
    int tx = tid & 15;

    float acc[8][4];
#pragma unroll
    for (int r = 0; r < 8; r++)
#pragma unroll
        for (int c = 0; c < 4; c++) acc[r][c] = 0.f;

    for (int k0 = 0; k0 < FEAT; k0 += 32) {
#pragma unroll
        for (int i = 0; i < 16; i++) {
            int l = tid + i * 256;
            int r = l >> 5, kk = l & 31;
            int gr = row0 + r;
            sf[r][kk] = (gr < N_ITEM) ? fea[gr * FEAT + k0 + kk] : 0.f;
        }
#pragma unroll
        for (int i = 0; i < 8; i++) {
            int l = tid + i * 256;
            int kk = l >> 6, c = l & 63;
            sw[kk][c] = w[(k0 + kk) * EMB + c];
        }
        __syncthreads();
#pragma unroll
        for (int kk = 0; kk < 32; kk++) {
            float4 wv = *(const float4*)&sw[kk][tx * 4];
#pragma unroll
            for (int r = 0; r < 8; r++) {
                float f = sf[ty * 8 + r][kk];
                acc[r][0] += f * wv.x;
                acc[r][1] += f * wv.y;
                acc[r][2] += f * wv.z;
                acc[r][3] += f * wv.w;
            }
        }
        __syncthreads();
    }

#pragma unroll
    for (int r = 0; r < 8; r++) {
        int gr = row0 + ty * 8 + r;
        float c0 = tanhf(acc[r][0] + b[tx * 4 + 0]);
        float c1 = tanhf(acc[r][1] + b[tx * 4 + 1]);
        float c2 = tanhf(acc[r][2] + b[tx * 4 + 2]);
        float c3 = tanhf(acc[r][3] + b[tx * 4 + 3]);
        float s = c0 * c0 + c1 * c1 + c2 * c2 + c3 * c3;
#pragma unroll
        for (int o = 1; o < 16; o <<= 1) s += __shfl_xor_sync(0xffffffffu, s, o);
        if (gr < N_ITEM) {
            int row = N_USER + gr;
            *(float4*)&g_ego[row * EMB + tx * 4] = make_float4(c0, c1, c2, c3);
            g_ego16[row * 32 + tx * 2 + 0] = __floats2bfloat162_rn(c0, c1);
            g_ego16[row * 32 + tx * 2 + 1] = __floats2bfloat162_rn(c2, c3);
            if (tx == 0) g_norm[row] = sqrtf(s);
        }
    }
}

// ---------------- fused SpMM + cosine-reweight, TWO rows per warp ----------
// lanes 0-15 -> row 2w, lanes 16-31 -> row 2w+1; 8B (2x bf16x2) per lane.
__global__ __launch_bounds__(256) void k_layerA(const __nv_bfloat162* __restrict__ xin,
                                                __nv_bfloat162* __restrict__ xout)
{
    int gwarp = (blockIdx.x * blockDim.x + threadIdx.x) >> 5;
    int lane = threadIdx.x & 31;
    int half = lane >> 4;
    int hl   = lane & 15;
    int row  = gwarp * 2 + half;
    if (row >= NTOT) return;                 // NTOT even: whole warp exits together

    int s = g_rowptr[row];
    int len = g_rowptr[row + 1] - s;
    int ml = max(len, __shfl_xor_sync(0xffffffffu, len, 16));

    const uint2* x2 = (const uint2*)xin;
    float a0 = 0.f, a1 = 0.f, a2 = 0.f, a3 = 0.f;
#pragma unroll 4
    for (int i = 0; i < ml; i++) {
        if (i < len) {
            int2 ed = __ldg(&g_edges[s + i]);
            float v = __int_as_float(ed.y);
            uint2 q = __ldg(&x2[ed.x * 16 + hl]);
            float2 f0 = __bfloat1622float2(*(__nv_bfloat162*)&q.x);
            float2 f1 = __bfloat1622float2(*(__nv_bfloat162*)&q.y);
            a0 += v * f0.x; a1 += v * f0.y;
            a2 += v * f1.x; a3 += v * f1.y;
        }
    }

    uint2 eq = ((const uint2*)g_ego16)[row * 16 + hl];
    float2 e0 = __bfloat1622float2(*(__nv_bfloat162*)&eq.x);
    float2 e1 = __bfloat1622float2(*(__nv_bfloat162*)&eq.y);
    float dot = a0 * e0.x + a1 * e0.y + a2 * e1.x + a3 * e1.y;
    float nn  = a0 * a0 + a1 * a1 + a2 * a2 + a3 * a3;
#pragma unroll
    for (int o = 8; o; o >>= 1) {            // 16-wide: stays within each half
        dot += __shfl_xor_sync(0xffffffffu, dot, o);
        nn  += __shfl_xor_sync(0xffffffffu, nn,  o);
    }
    float wgt = dot / fmaxf(sqrtf(nn) * g_norm[row], EPS_F);

    uint2 oq;
    *(__nv_bfloat162*)&oq.x = __floats2bfloat162_rn(wgt * a0, wgt * a1);
    *(__nv_bfloat162*)&oq.y = __floats2bfloat162_rn(wgt * a2, wgt * a3);
    ((uint2*)xout)[row * 16 + hl] = oq;
}

// final layer: SpMM + reweight + fused total sum  out = ego + x1 + x2 + x3 + x4
__global__ __launch_bounds__(256) void k_layerB(float* __restrict__ out)
{
    int gwarp = (blockIdx.x * blockDim.x + threadIdx.x) >> 5;
    int lane = threadIdx.x & 31;
    int half = lane >> 4;
    int hl   = lane & 15;
    int row  = gwarp * 2 + half;
    if (row >= NTOT) return;

    int s = g_rowptr[row];
    int len = g_rowptr[row + 1] - s;
    int ml = max(len, __shfl_xor_sync(0xffffffffu, len, 16));

    const uint2* x2 = (const uint2*)g_x3;
    float a0 = 0.f, a1 = 0.f, a2 = 0.f, a3 = 0.f;
#pragma unroll 4
    for (int i = 0; i < ml; i++) {
        if (i < len) {
            int2 ed = __ldg(&g_edges[s + i]);
            float v = __int_as_float(ed.y);
            uint2 q = __ldg(&x2[ed.x * 16 + hl]);
            float2 f0 = __bfloat1622float2(*(__nv_bfloat162*)&q.x);
            float2 f1 = __bfloat1622float2(*(__nv_bfloat162*)&q.y);
            a0 += v * f0.x; a1 += v * f0.y;
            a2 += v * f1.x; a3 += v * f1.y;
        }
    }

    float4 ev = ((const float4*)g_ego)[row * 16 + hl];
    float dot = a0 * ev.x + a1 * ev.y + a2 * ev.z + a3 * ev.w;
    float nn  = a0 * a0 + a1 * a1 + a2 * a2 + a3 * a3;
#pragma unroll
    for (int o = 8; o; o >>= 1) {
        dot += __shfl_xor_sync(0xffffffffu, dot, o);
        nn  += __shfl_xor_sync(0xffffffffu, nn,  o);
    }
    float wgt = dot / fmaxf(sqrtf(nn) * g_norm[row], EPS_F);

    int idx = row * 16 + hl;
    uint2 q1 = ((const uint2*)g_x1)[idx];
    uint2 q2 = ((const uint2*)g_x2)[idx];
    uint2 q3 = ((const uint2*)g_x3)[idx];
    float2 v10 = __bfloat1622float2(*(__nv_bfloat162*)&q1.x);
    float2 v11 = __bfloat1622float2(*(__nv_bfloat162*)&q1.y);
    float2 v20 = __bfloat1622float2(*(__nv_bfloat162*)&q2.x);
    float2 v21 = __bfloat1622float2(*(__nv_bfloat162*)&q2.y);
    float2 v30 = __bfloat1622float2(*(__nv_bfloat162*)&q3.x);
    float2 v31 = __bfloat1622float2(*(__nv_bfloat162*)&q3.y);
    float4 r;
    r.x = ev.x + v10.x + v20.x + v30.x + wgt * a0;
    r.y = ev.y + v10.y + v20.y + v30.y + wgt * a1;
    r.z = ev.z + v11.x + v21.x + v31.x + wgt * a2;
    r.w = ev.w + v11.y + v21.y + v31.y + wgt * a3;
    ((float4*)out)[idx] = r;
}

// ---------------- side stream (created at static-init; never destroyed) ----
namespace {
struct SideStream {
    cudaStream_t s = 0;
    cudaEvent_t fork = 0, join = 0;
    SideStream() {
        if (cudaStreamCreateWithFlags(&s, cudaStreamNonBlocking) != cudaSuccess) s = 0;
        if (cudaEventCreateWithFlags(&fork, cudaEventDisableTiming) != cudaSuccess) fork = 0;
        if (cudaEventCreateWithFlags(&join, cudaEventDisableTiming) != cudaSuccess) join = 0;
        if (!fork || !join) s = 0;
    }
};
SideStream g_ss;
}

// ---------------- launch ----------------
extern "C" void kernel_launch(void* const* d_in, const int* in_sizes, int n_in,
                              void* d_out, int out_size)
{
    const float* user   = (const float*)d_in[0];
    const float* item   = (const float*)d_in[1];
    const float* prompt = (const float*)d_in[2];
    const float* mw     = (const float*)d_in[3];
    const float* mb     = (const float*)d_in[4];
    const int*   rows   = (const int*)d_in[5];
    const int*   cols   = (const int*)d_in[6];
    const float* vals   = (const float*)d_in[7];
    float* out = (float*)d_out;

    void *p16, *p1, *p2, *p3;
    cudaGetSymbolAddress(&p16, g_ego16);
    cudaGetSymbolAddress(&p1,  g_x1);
    cudaGetSymbolAddress(&p2,  g_x2);
    cudaGetSymbolAddress(&p3,  g_x3);
    __nv_bfloat162* ego16 = (__nv_bfloat162*)p16;
    __nv_bfloat162* x1    = (__nv_bfloat162*)p1;
    __nv_bfloat162* x2    = (__nv_bfloat162*)p2;
    __nv_bfloat162* x3    = (__nv_bfloat162*)p3;

    const int SCAN_BLOCKS = (NTOT + 1023) / 1024;   // 147
    cudaStream_t sb = g_ss.s ? g_ss.s : (cudaStream_t)0;
    bool split = (g_ss.s != 0);

    if (split) {
        cudaEventRecord(g_ss.fork, 0);
        cudaStreamWaitEvent(g_ss.s, g_ss.fork, 0);
    }

    // chain A (stream 0): CSR build
    k_zero   <<<(NTOT + 255) / 256, 256>>>();
    k_hist   <<<2048, 256>>>(rows);
    k_scan1  <<<SCAN_BLOCKS, 1024>>>();
    k_scan2  <<<1, 256>>>(SCAN_BLOCKS);
    k_scan3  <<<SCAN_BLOCKS, 1024>>>();
    k_scatter<<<2048, 256>>>(rows, cols, vals);

    // chain B (side stream): ego + norms + bf16 mirror
    k_ego_user<<<(N_USER * 32 + 255) / 256, 256, 0, sb>>>(user, prompt);
    k_item    <<<(N_ITEM + 127) / 128, 256, 0, sb>>>(item, mw, mb);

    if (split) {
        cudaEventRecord(g_ss.join, g_ss.s);
        cudaStreamWaitEvent(0, g_ss.join, 0);
    }

    // 4 propagation layers — two rows per warp
    const int LB = (NTOT / 2 * 32 + 255) / 256;   // 9375 blocks
    k_layerA<<<LB, 256>>>(ego16, x1);
    k_layerA<<<LB, 256>>>(x1,    x2);
    k_layerA<<<LB, 256>>>(x2,    x3);
    k_layerB<<<LB, 256>>>(out);
}

// round 7
// speedup vs baseline: 1.8319x; 1.0044x over previous
#include <cuda_runtime.h>
#include <cuda_bf16.h>

#define N_USER 100000
#define N_ITEM 50000
#define NTOT   150000
#define EMB    64
#define FEAT   384
#define NNZ    2400000
#define EPS_F  1e-8f

// ---------------- device scratch (static, no allocations) ----------------
__device__ float          g_ego[NTOT * EMB];       // 38.4 MB fp32
__device__ __nv_bfloat162 g_ego16[NTOT * 32];      // 19.2 MB bf16
__device__ __nv_bfloat162 g_x1[NTOT * 32];
__device__ __nv_bfloat162 g_x2[NTOT * 32];
__device__ __nv_bfloat162 g_x3[NTOT * 32];
__device__ float g_norm[NTOT];
__device__ int   g_counts[NTOT];
__device__ int   g_cursor[NTOT];
__device__ int   g_rowptr[NTOT + 1];
__device__ int2  g_edges[NNZ];
__device__ int   g_bsum[256];

// ---------------- CSR build (R2/R4 proven path — DO NOT TOUCH) ----------------
__global__ void k_zero()
{
    int i = blockIdx.x * blockDim.x + threadIdx.x;
    if (i < NTOT) { g_counts[i] = 0; g_cursor[i] = 0; }
}

__global__ void k_hist(const int* __restrict__ rows)
{
    int stride = gridDim.x * blockDim.x;
    for (int e = blockIdx.x * blockDim.x + threadIdx.x; e < NNZ; e += stride)
        atomicAdd(&g_counts[rows[e]], 1);
}

__global__ void k_scan1()
{
    __shared__ int sh[1024];
    int tid = threadIdx.x;
    int gid = blockIdx.x * 1024 + tid;
    int v = (gid < NTOT) ? g_counts[gid] : 0;
    sh[tid] = v;
    __syncthreads();
    for (int o = 1; o < 1024; o <<= 1) {
        int t = (tid >= o) ? sh[tid - o] : 0;
        __syncthreads();
        if (tid >= o) sh[tid] += t;
        __syncthreads();
    }
    if (gid < NTOT) g_rowptr[gid] = sh[tid] - v;
    if (tid == 1023) g_bsum[blockIdx.x] = sh[1023];
}

__global__ void k_scan2(int nb)
{
    __shared__ int sh[256];
    int tid = threadIdx.x;
    int v = (tid < nb) ? g_bsum[tid] : 0;
    sh[tid] = v;
    __syncthreads();
    for (int o = 1; o < 256; o <<= 1) {
        int t = (tid >= o) ? sh[tid - o] : 0;
        __syncthreads();
        if (tid >= o) sh[tid] += t;
        __syncthreads();
    }
    g_bsum[tid] = sh[tid] - v;
}

__global__ void k_scan3()
{
    int gid = blockIdx.x * 1024 + threadIdx.x;
    if (gid < NTOT) g_rowptr[gid] += g_bsum[blockIdx.x];
    if (gid == 0) g_rowptr[NTOT] = NNZ;
}

__global__ void k_scatter(const int* __restrict__ rows,
                          const int* __restrict__ cols,
                          const float* __restrict__ vals)
{
    int stride = gridDim.x * blockDim.x;
    for (int e = blockIdx.x * blockDim.x + threadIdx.x; e < NNZ; e += stride) {
        int r = rows[e];
        int p = g_rowptr[r] + atomicAdd(&g_cursor[r], 1);
        g_edges[p] = make_int2(cols[e], __float_as_int(vals[e]));
    }
}

// ---------------- ego construction (fused norm + bf16) ----------------
__global__ void k_ego_user(const float* __restrict__ user,
                           const float* __restrict__ prompt)
{
    __shared__ float ps[EMB];
    int tid = threadIdx.x;
    if (tid < EMB) {
        float s = 0.f;
#pragma unroll
        for (int p = 0; p < 8; p++) s += prompt[p * EMB + tid];
        ps[tid] = s;
    }
    __syncthreads();
    int warp = (blockIdx.x * blockDim.x + tid) >> 5;
    int lane = tid & 31;
    if (warp >= N_USER) return;
    float2 u = ((const float2*)user)[warp * 32 + lane];
    float2 p2 = *(const float2*)&ps[lane * 2];
    float vx = u.x + p2.x, vy = u.y + p2.y;
    ((float2*)g_ego)[warp * 32 + lane] = make_float2(vx, vy);
    g_ego16[warp * 32 + lane] = __floats2bfloat162_rn(vx, vy);
    float s = vx * vx + vy * vy;
#pragma unroll
    for (int o = 16; o; o >>= 1) s += __shfl_xor_sync(0xffffffffu, s, o);
    if (lane == 0) g_norm[warp] = sqrtf(s);
}

// R2-proven tiled SGEMM + fused tanh/norm/bf16 epilogue (R4 state)
__global__ __launch_bounds__(256) void k_item(const float* __restrict__ fea,
                                              const float* __restrict__ w,
                                              const float* __restrict__ b)
{
    __shared__ float sf[128][33];
    __shared__ float sw[32][64];
    int tid = threadIdx.x;
    int row0 = blockIdx.x * 128;
    int ty = tid >> 4;
    int tx = tid & 15;

    float acc[8][4];
#pragma unroll
    for (int r = 0; r < 8; r++)
#pragma unroll
        for (int c = 0; c < 4; c++) acc[r][c] = 0.f;

    for (int k0 = 0; k0 < FEAT; k0 += 32) {
#pragma unroll
        for (int i = 0; i < 16; i++) {
            int l = tid + i * 256;
            int r = l >> 5, kk = l & 31;
            int gr = row0 + r;
            sf[r][kk] = (gr < N_ITEM) ? fea[gr * FEAT + k0 + kk] : 0.f;
        }
#pragma unroll
        for (int i = 0; i < 8; i++) {
            int l = tid + i * 256;
            int kk = l >> 6, c = l & 63;
            sw[kk][c] = w[(k0 + kk) * EMB + c];
        }
        __syncthreads();
#pragma unroll
        for (int kk = 0; kk < 32; kk++) {
            float4 wv = *(const float4*)&sw[kk][tx * 4];
#pragma unroll
            for (int r = 0; r < 8; r++) {
                float f = sf[ty * 8 + r][kk];
                acc[r][0] += f * wv.x;
                acc[r][1] += f * wv.y;
                acc[r][2] += f * wv.z;
                acc[r][3] += f * wv.w;
            }
        }
        __syncthreads();
    }

#pragma unroll
    for (int r = 0; r < 8; r++) {
        int gr = row0 + ty * 8 + r;
        float c0 = tanhf(acc[r][0] + b[tx * 4 + 0]);
        float c1 = tanhf(acc[r][1] + b[tx * 4 + 1]);
        float c2 = tanhf(acc[r][2] + b[tx * 4 + 2]);
        float c3 = tanhf(acc[r][3] + b[tx * 4 + 3]);
        float s = c0 * c0 + c1 * c1 + c2 * c2 + c3 * c3;
#pragma unroll
        for (int o = 1; o < 16; o <<= 1) s += __shfl_xor_sync(0xffffffffu, s, o);
        if (gr < N_ITEM) {
            int row = N_USER + gr;
            *(float4*)&g_ego[row * EMB + tx * 4] = make_float4(c0, c1, c2, c3);
            g_ego16[row * 32 + tx * 2 + 0] = __floats2bfloat162_rn(c0, c1);
            g_ego16[row * 32 + tx * 2 + 1] = __floats2bfloat162_rn(c2, c3);
            if (tx == 0) g_norm[row] = sqrtf(s);
        }
    }
}

// ---------------- fused SpMM + cosine-reweight, FOUR rows per warp ---------
// lanes 8g..8g+7 -> row 4w+g; 16B (uint4 = 4x bf16x2 = 8 elems) per lane.
__global__ __launch_bounds__(256) void k_layerA(const __nv_bfloat162* __restrict__ xin,
                                                __nv_bfloat162* __restrict__ xout)
{
    int gwarp = (blockIdx.x * blockDim.x + threadIdx.x) >> 5;
    int lane = threadIdx.x & 31;
    int grp  = lane >> 3;      // 0..3
    int gl   = lane & 7;       // 0..7
    int row  = gwarp * 4 + grp;
    if (row >= NTOT) return;   // NTOT % 4 == 0: whole warp exits together

    int s = g_rowptr[row];
    int len = g_rowptr[row + 1] - s;
    int ml = max(len, __shfl_xor_sync(0xffffffffu, len, 8));
    ml = max(ml, __shfl_xor_sync(0xffffffffu, ml, 16));

    const uint4* x4 = (const uint4*)xin;          // 8 uint4 per row
    float a0 = 0.f, a1 = 0.f, a2 = 0.f, a3 = 0.f;
    float a4 = 0.f, a5 = 0.f, a6 = 0.f, a7 = 0.f;
#pragma unroll 4
    for (int i = 0; i < ml; i++) {
        if (i < len) {
            int2 ed = __ldg(&g_edges[s + i]);
            float v = __int_as_float(ed.y);
            uint4 q = __ldg(&x4[ed.x * 8 + gl]);
            float2 f0 = __bfloat1622float2(*(__nv_bfloat162*)&q.x);
            float2 f1 = __bfloat1622float2(*(__nv_bfloat162*)&q.y);
            float2 f2 = __bfloat1622float2(*(__nv_bfloat162*)&q.z);
            float2 f3 = __bfloat1622float2(*(__nv_bfloat162*)&q.w);
            a0 += v * f0.x; a1 += v * f0.y;
            a2 += v * f1.x; a3 += v * f1.y;
            a4 += v * f2.x; a5 += v * f2.y;
            a6 += v * f3.x; a7 += v * f3.y;
        }
    }

    uint4 eq = ((const uint4*)g_ego16)[row * 8 + gl];
    float2 e0 = __bfloat1622float2(*(__nv_bfloat162*)&eq.x);
    float2 e1 = __bfloat1622float2(*(__nv_bfloat162*)&eq.y);
    float2 e2 = __bfloat1622float2(*(__nv_bfloat162*)&eq.z);
    float2 e3 = __bfloat1622float2(*(__nv_bfloat162*)&eq.w);
    float dot = a0 * e0.x + a1 * e0.y + a2 * e1.x + a3 * e1.y
              + a4 * e2.x + a5 * e2.y + a6 * e3.x + a7 * e3.y;
    float nn  = a0 * a0 + a1 * a1 + a2 * a2 + a3 * a3
              + a4 * a4 + a5 * a5 + a6 * a6 + a7 * a7;
#pragma unroll
    for (int o = 4; o; o >>= 1) {            // 8-wide: stays within each group
        dot += __shfl_xor_sync(0xffffffffu, dot, o);
        nn  += __shfl_xor_sync(0xffffffffu, nn,  o);
    }
    float wgt = dot / fmaxf(sqrtf(nn) * g_norm[row], EPS_F);

    uint4 oq;
    *(__nv_bfloat162*)&oq.x = __floats2bfloat162_rn(wgt * a0, wgt * a1);
    *(__nv_bfloat162*)&oq.y = __floats2bfloat162_rn(wgt * a2, wgt * a3);
    *(__nv_bfloat162*)&oq.z = __floats2bfloat162_rn(wgt * a4, wgt * a5);
    *(__nv_bfloat162*)&oq.w = __floats2bfloat162_rn(wgt * a6, wgt * a7);
    ((uint4*)xout)[row * 8 + gl] = oq;
}

// final layer: SpMM + reweight + fused total sum  out = ego + x1 + x2 + x3 + x4
__global__ __launch_bounds__(256) void k_layerB(float* __restrict__ out)
{
    int gwarp = (blockIdx.x * blockDim.x + threadIdx.x) >> 5;
    int lane = threadIdx.x & 31;
    int grp  = lane >> 3;
    int gl   = lane & 7;
    int row  = gwarp * 4 + grp;
    if (row >= NTOT) return;

    int s = g_rowptr[row];
    int len = g_rowptr[row + 1] - s;
    int ml = max(len, __shfl_xor_sync(0xffffffffu, len, 8));
    ml = max(ml, __shfl_xor_sync(0xffffffffu, ml, 16));

    const uint4* x4 = (const uint4*)g_x3;
    float a0 = 0.f, a1 = 0.f, a2 = 0.f, a3 = 0.f;
    float a4 = 0.f, a5 = 0.f, a6 = 0.f, a7 = 0.f;
#pragma unroll 4
    for (int i = 0; i < ml; i++) {
        if (i < len) {
            int2 ed = __ldg(&g_edges[s + i]);
            float v = __int_as_float(ed.y);
            uint4 q = __ldg(&x4[ed.x * 8 + gl]);
            float2 f0 = __bfloat1622float2(*(__nv_bfloat162*)&q.x);
            float2 f1 = __bfloat1622float2(*(__nv_bfloat162*)&q.y);
            float2 f2 = __bfloat1622float2(*(__nv_bfloat162*)&q.z);
            float2 f3 = __bfloat1622float2(*(__nv_bfloat162*)&q.w);
            a0 += v * f0.x; a1 += v * f0.y;
            a2 += v * f1.x; a3 += v * f1.y;
            a4 += v * f2.x; a5 += v * f2.y;
            a6 += v * f3.x; a7 += v * f3.y;
        }
    }

    // fp32 ego: row = 256B = 16 float4; this lane covers float4 slots 2*gl, 2*gl+1
    int eidx = row * 16 + gl * 2;
    float4 ea = ((const float4*)g_ego)[eidx];
    float4 eb = ((const float4*)g_ego)[eidx + 1];
    float dot = a0 * ea.x + a1 * ea.y + a2 * ea.z + a3 * ea.w
              + a4 * eb.x + a5 * eb.y + a6 * eb.z + a7 * eb.w;
    float nn  = a0 * a0 + a1 * a1 + a2 * a2 + a3 * a3
              + a4 * a4 + a5 * a5 + a6 * a6 + a7 * a7;
#pragma unroll
    for (int o = 4; o; o >>= 1) {
        dot += __shfl_xor_sync(0xffffffffu, dot, o);
        nn  += __shfl_xor_sync(0xffffffffu, nn,  o);
    }
    float wgt = dot / fmaxf(sqrtf(nn) * g_norm[row], EPS_F);

    int idx = row * 8 + gl;
    uint4 q1 = ((const uint4*)g_x1)[idx];
    uint4 q2 = ((const uint4*)g_x2)[idx];
    uint4 q3 = ((const uint4*)g_x3)[idx];
    float2 p10 = __bfloat1622float2(*(__nv_bfloat162*)&q1.x);
    float2 p11 = __bfloat1622float2(*(__nv_bfloat162*)&q1.y);
    float2 p12 = __bfloat1622float2(*(__nv_bfloat162*)&q1.z);
    float2 p13 = __bfloat1622float2(*(__nv_bfloat162*)&q1.w);
    float2 p20 = __bfloat1622float2(*(__nv_bfloat162*)&q2.x);
    float2 p21 = __bfloat1622float2(*(__nv_bfloat162*)&q2.y);
    float2 p22 = __bfloat1622float2(*(__nv_bfloat162*)&q2.z);
    float2 p23 = __bfloat1622float2(*(__nv_bfloat162*)&q2.w);
    float2 p30 = __bfloat1622float2(*(__nv_bfloat162*)&q3.x);
    float2 p31 = __bfloat1622float2(*(__nv_bfloat162*)&q3.y);
    float2 p32 = __bfloat1622float2(*(__nv_bfloat162*)&q3.z);
    float2 p33 = __bfloat1622float2(*(__nv_bfloat162*)&q3.w);

    float4 ra, rb;
    ra.x = ea.x + p10.x + p20.x + p30.x + wgt * a0;
    ra.y = ea.y + p10.y + p20.y + p30.y + wgt * a1;
    ra.z = ea.z + p11.x + p21.x + p31.x + wgt * a2;
    ra.w = ea.w + p11.y + p21.y + p31.y + wgt * a3;
    rb.x = eb.x + p12.x + p22.x + p32.x + wgt * a4;
    rb.y = eb.y + p12.y + p22.y + p32.y + wgt * a5;
    rb.z = eb.z + p13.x + p23.x + p33.x + wgt * a6;
    rb.w = eb.w + p13.y + p23.y + p33.y + wgt * a7;
    ((float4*)out)[eidx]     = ra;
    ((float4*)out)[eidx + 1] = rb;
}

// ---------------- side stream (created at static-init; never destroyed) ----
namespace {
struct SideStream {
    cudaStream_t s = 0;
    cudaEvent_t fork = 0, join = 0;
    SideStream() {
        if (cudaStreamCreateWithFlags(&s, cudaStreamNonBlocking) != cudaSuccess) s = 0;
        if (cudaEventCreateWithFlags(&fork, cudaEventDisableTiming) != cudaSuccess) fork = 0;
        if (cudaEventCreateWithFlags(&join, cudaEventDisableTiming) != cudaSuccess) join = 0;
        if (!fork || !join) s = 0;
    }
};
SideStream g_ss;
}

// ---------------- launch ----------------
extern "C" void kernel_launch(void* const* d_in, const int* in_sizes, int n_in,
                              void* d_out, int out_size)
{
    const float* user   = (const float*)d_in[0];
    const float* item   = (const float*)d_in[1];
    const float* prompt = (const float*)d_in[2];
    const float* mw     = (const float*)d_in[3];
    const float* mb     = (const float*)d_in[4];
    const int*   rows   = (const int*)d_in[5];
    const int*   cols   = (const int*)d_in[6];
    const float* vals   = (const float*)d_in[7];
    float* out = (float*)d_out;

    void *p16, *p1, *p2, *p3;
    cudaGetSymbolAddress(&p16, g_ego16);
    cudaGetSymbolAddress(&p1,  g_x1);
    cudaGetSymbolAddress(&p2,  g_x2);
    cudaGetSymbolAddress(&p3,  g_x3);
    __nv_bfloat162* ego16 = (__nv_bfloat162*)p16;
    __nv_bfloat162* x1    = (__nv_bfloat162*)p1;
    __nv_bfloat162* x2    = (__nv_bfloat162*)p2;
    __nv_bfloat162* x3    = (__nv_bfloat162*)p3;

    const int SCAN_BLOCKS = (NTOT + 1023) / 1024;   // 147
    cudaStream_t sb = g_ss.s ? g_ss.s : (cudaStream_t)0;
    bool split = (g_ss.s != 0);

    if (split) {
        cudaEventRecord(g_ss.fork, 0);
        cudaStreamWaitEvent(g_ss.s, g_ss.fork, 0);
    }

    // chain A (stream 0): CSR build
    k_zero   <<<(NTOT + 255) / 256, 256>>>();
    k_hist   <<<2048, 256>>>(rows);
    k_scan1  <<<SCAN_BLOCKS, 1024>>>();
    k_scan2  <<<1, 256>>>(SCAN_BLOCKS);
    k_scan3  <<<SCAN_BLOCKS, 1024>>>();
    k_scatter<<<2048, 256>>>(rows, cols, vals);

    // chain B (side stream): ego + norms + bf16 mirror
    k_ego_user<<<(N_USER * 32 + 255) / 256, 256, 0, sb>>>(user, prompt);
    k_item    <<<(N_ITEM + 127) / 128, 256, 0, sb>>>(item, mw, mb);

    if (split) {
        cudaEventRecord(g_ss.join, g_ss.s);
        cudaStreamWaitEvent(0, g_ss.join, 0);
    }

    // 4 propagation layers — four rows per warp
    const int LB = (NTOT / 4 * 32 + 255) / 256;   // 4688 blocks
    k_layerA<<<LB, 256>>>(ego16, x1);
    k_layerA<<<LB, 256>>>(x1,    x2);
    k_layerA<<<LB, 256>>>(x2,    x3);
    k_layerB<<<LB, 256>>>(out);
}

// round 8
// speedup vs baseline: 1.9694x; 1.0751x over previous
#include <cuda_runtime.h>
#include <cuda_bf16.h>

#define N_USER 100000
#define N_ITEM 50000
#define NTOT   150000
#define EMB    64
#define FEAT   384
#define NNZ    2400000
#define EPS_F  1e-8f

// ---------------- device scratch (static, no allocations) ----------------
__device__ float          g_ego[NTOT * EMB];       // 38.4 MB fp32
__device__ __nv_bfloat162 g_ego16[NTOT * 32];      // 19.2 MB bf16
__device__ __nv_bfloat162 g_x1[NTOT * 32];
__device__ __nv_bfloat162 g_x2[NTOT * 32];
__device__ __nv_bfloat162 g_x3[NTOT * 32];
__device__ float g_norm[NTOT];
__device__ int   g_counts[NTOT];
__device__ int   g_rank[NNZ];                      // per-edge rank within row
__device__ int   g_rowptr[NTOT + 1];
__device__ int2  g_edges[NNZ];
__device__ int   g_bsum[256];

// ---------------- CSR build ----------------
__global__ void k_zero()
{
    int i = blockIdx.x * blockDim.x + threadIdx.x;
    if (i < NTOT) g_counts[i] = 0;
}

// histogram + per-edge rank (atomic return value) — replaces cursor atomics
__global__ void k_hist(const int* __restrict__ rows)
{
    int stride = gridDim.x * blockDim.x;
    for (int e = blockIdx.x * blockDim.x + threadIdx.x; e < NNZ; e += stride)
        g_rank[e] = atomicAdd(&g_counts[rows[e]], 1);
}

__global__ void k_scan1()
{
    __shared__ int sh[1024];
    int tid = threadIdx.x;
    int gid = blockIdx.x * 1024 + tid;
    int v = (gid < NTOT) ? g_counts[gid] : 0;
    sh[tid] = v;
    __syncthreads();
    for (int o = 1; o < 1024; o <<= 1) {
        int t = (tid >= o) ? sh[tid - o] : 0;
        __syncthreads();
        if (tid >= o) sh[tid] += t;
        __syncthreads();
    }
    if (gid < NTOT) g_rowptr[gid] = sh[tid] - v;
    if (tid == 1023) g_bsum[blockIdx.x] = sh[1023];
}

__global__ void k_scan2(int nb)
{
    __shared__ int sh[256];
    int tid = threadIdx.x;
    int v = (tid < nb) ? g_bsum[tid] : 0;
    sh[tid] = v;
    __syncthreads();
    for (int o = 1; o < 256; o <<= 1) {
        int t = (tid >= o) ? sh[tid - o] : 0;
        __syncthreads();
        if (tid >= o) sh[tid] += t;
        __syncthreads();
    }
    g_bsum[tid] = sh[tid] - v;
}

__global__ void k_scan3()
{
    int gid = blockIdx.x * 1024 + threadIdx.x;
    if (gid < NTOT) g_rowptr[gid] += g_bsum[blockIdx.x];
    if (gid == 0) g_rowptr[NTOT] = NNZ;
}

// atomic-free scatter using precomputed ranks
__global__ void k_scatter(const int* __restrict__ rows,
                          const int* __restrict__ cols,
                          const float* __restrict__ vals)
{
    int stride = gridDim.x * blockDim.x;
    for (int e = blockIdx.x * blockDim.x + threadIdx.x; e < NNZ; e += stride) {
        int r = rows[e];
        int p = g_rowptr[r] + g_rank[e];
        g_edges[p] = make_int2(cols[e], __float_as_int(vals[e]));
    }
}

// ---------------- ego construction (fused norm + bf16) ----------------
__global__ void k_ego_user(const float* __restrict__ user,
                           const float* __restrict__ prompt)
{
    __shared__ float ps[EMB];
    int tid = threadIdx.x;
    if (tid < EMB) {
        float s = 0.f;
#pragma unroll
        for (int p = 0; p < 8; p++) s += prompt[p * EMB + tid];
        ps[tid] = s;
    }
    __syncthreads();
    int warp = (blockIdx.x * blockDim.x + tid) >> 5;
    int lane = tid & 31;
    if (warp >= N_USER) return;
    float2 u = ((const float2*)user)[warp * 32 + lane];
    float2 p2 = *(const float2*)&ps[lane * 2];
    float vx = u.x + p2.x, vy = u.y + p2.y;
    ((float2*)g_ego)[warp * 32 + lane] = make_float2(vx, vy);
    g_ego16[warp * 32 + lane] = __floats2bfloat162_rn(vx, vy);
    float s = vx * vx + vy * vy;
#pragma unroll
    for (int o = 16; o; o >>= 1) s += __shfl_xor_sync(0xffffffffu, s, o);
    if (lane == 0) g_norm[warp] = sqrtf(s);
}

// R2-proven tiled SGEMM + fused tanh/norm/bf16 epilogue
__global__ __launch_bounds__(256) void k_item(const float* __restrict__ fea,
                                              const float* __restrict__ w,
                                              const float* __restrict__ b)
{
    __shared__ float sf[128][33];
    __shared__ float sw[32][64];
    int tid = threadIdx.x;
    int row0 = blockIdx.x * 128;
    int ty = tid >> 4;
    int tx = tid & 15;

    float acc[8][4];
#pragma unroll
    for (int r = 0; r < 8; r++)
#pragma unroll
        for (int c = 0; c < 4; c++) acc[r][c] = 0.f;

    for (int k0 = 0; k0 < FEAT; k0 += 32) {
#pragma unroll
        for (int i = 0; i < 16; i++) {
            int l = tid + i * 256;
            int r = l >> 5, kk = l & 31;
            int gr = row0 + r;
            sf[r][kk] = (gr < N_ITEM) ? fea[gr * FEAT + k0 + kk] : 0.f;
        }
#pragma unroll
        for (int i = 0; i < 8; i++) {
            int l = tid + i * 256;
            int kk = l >> 6, c = l & 63;
            sw[kk][c] = w[(k0 + kk) * EMB + c];
        }
        __syncthreads();
#pragma unroll
        for (int kk = 0; kk < 32; kk++) {
            float4 wv = *(const float4*)&sw[kk][tx * 4];
#pragma unroll
            for (int r = 0; r < 8; r++) {
                float f = sf[ty * 8 + r][kk];
                acc[r][0] += f * wv.x;
                acc[r][1] += f * wv.y;
                acc[r][2] += f * wv.z;
                acc[r][3] += f * wv.w;
            }
        }
        __syncthreads();
    }

#pragma unroll
    for (int r = 0; r < 8; r++) {
        int gr = row0 + ty * 8 + r;
        float c0 = tanhf(acc[r][0] + b[tx * 4 + 0]);
        float c1 = tanhf(acc[r][1] + b[tx * 4 + 1]);
        float c2 = tanhf(acc[r][2] + b[tx * 4 + 2]);
        float c3 = tanhf(acc[r][3] + b[tx * 4 + 3]);
        float s = c0 * c0 + c1 * c1 + c2 * c2 + c3 * c3;
#pragma unroll
        for (int o = 1; o < 16; o <<= 1) s += __shfl_xor_sync(0xffffffffu, s, o);
        if (gr < N_ITEM) {
            int row = N_USER + gr;
            *(float4*)&g_ego[row * EMB + tx * 4] = make_float4(c0, c1, c2, c3);
            g_ego16[row * 32 + tx * 2 + 0] = __floats2bfloat162_rn(c0, c1);
            g_ego16[row * 32 + tx * 2 + 1] = __floats2bfloat162_rn(c2, c3);
            if (tx == 0) g_norm[row] = sqrtf(s);
        }
    }
}

// ---------------- fused SpMM + cosine-reweight, 4 rows/warp, batch-8 ------
// lanes 8g..8g+7 -> row 4w+g; 16B per lane. Edges loaded 8-at-a-time
// coalesced, broadcast via shfl; padding lanes carry val=0 (adds +0.0f).
__global__ __launch_bounds__(256) void k_layerA(const __nv_bfloat162* __restrict__ xin,
                                                __nv_bfloat162* __restrict__ xout)
{
    int gwarp = (blockIdx.x * blockDim.x + threadIdx.x) >> 5;
    int lane = threadIdx.x & 31;
    int gl   = lane & 7;       // 0..7 within group
    int gb   = lane & 24;      // group base lane (grp*8)
    int row  = gwarp * 4 + (lane >> 3);
    if (row >= NTOT) return;   // NTOT % 4 == 0: uniform exit

    int s = g_rowptr[row];
    int len = g_rowptr[row + 1] - s;
    int ml = max(len, __shfl_xor_sync(0xffffffffu, len, 8));
    ml = max(ml, __shfl_xor_sync(0xffffffffu, ml, 16));

    const uint4* x4 = (const uint4*)xin;
    float a0 = 0.f, a1 = 0.f, a2 = 0.f, a3 = 0.f;
    float a4 = 0.f, a5 = 0.f, a6 = 0.f, a7 = 0.f;
    for (int base = 0; base < ml; base += 8) {
        int i = base + gl;
        int2 myed = (i < len) ? __ldg(&g_edges[s + i]) : make_int2(0, 0);
#pragma unroll
        for (int j = 0; j < 8; j++) {
            int c  = __shfl_sync(0xffffffffu, myed.x, gb + j);
            int vb = __shfl_sync(0xffffffffu, myed.y, gb + j);
            float v = __int_as_float(vb);
            uint4 q = __ldg(&x4[c * 8 + gl]);
            float2 f0 = __bfloat1622float2(*(__nv_bfloat162*)&q.x);
            float2 f1 = __bfloat1622float2(*(__nv_bfloat162*)&q.y);
            float2 f2 = __bfloat1622float2(*(__nv_bfloat162*)&q.z);
            float2 f3 = __bfloat1622float2(*(__nv_bfloat162*)&q.w);
            a0 += v * f0.x; a1 += v * f0.y;
            a2 += v * f1.x; a3 += v * f1.y;
            a4 += v * f2.x; a5 += v * f2.y;
            a6 += v * f3.x; a7 += v * f3.y;
        }
    }

    uint4 eq = ((const uint4*)g_ego16)[row * 8 + gl];
    float2 e0 = __bfloat1622float2(*(__nv_bfloat162*)&eq.x);
    float2 e1 = __bfloat1622float2(*(__nv_bfloat162*)&eq.y);
    float2 e2 = __bfloat1622float2(*(__nv_bfloat162*)&eq.z);
    float2 e3 = __bfloat1622float2(*(__nv_bfloat162*)&eq.w);
    float dot = a0 * e0.x + a1 * e0.y + a2 * e1.x + a3 * e1.y
              + a4 * e2.x + a5 * e2.y + a6 * e3.x + a7 * e3.y;
    float nn  = a0 * a0 + a1 * a1 + a2 * a2 + a3 * a3
              + a4 * a4 + a5 * a5 + a6 * a6 + a7 * a7;
#pragma unroll
    for (int o = 4; o; o >>= 1) {
        dot += __shfl_xor_sync(0xffffffffu, dot, o);
        nn  += __shfl_xor_sync(0xffffffffu, nn,  o);
    }
    float wgt = dot / fmaxf(sqrtf(nn) * g_norm[row], EPS_F);

    uint4 oq;
    *(__nv_bfloat162*)&oq.x = __floats2bfloat162_rn(wgt * a0, wgt * a1);
    *(__nv_bfloat162*)&oq.y = __floats2bfloat162_rn(wgt * a2, wgt * a3);
    *(__nv_bfloat162*)&oq.z = __floats2bfloat162_rn(wgt * a4, wgt * a5);
    *(__nv_bfloat162*)&oq.w = __floats2bfloat162_rn(wgt * a6, wgt * a7);
    ((uint4*)xout)[row * 8 + gl] = oq;
}

// final layer: SpMM + reweight + fused total sum  out = ego + x1 + x2 + x3 + x4
__global__ __launch_bounds__(256) void k_layerB(float* __restrict__ out)
{
    int gwarp = (blockIdx.x * blockDim.x + threadIdx.x) >> 5;
    int lane = threadIdx.x & 31;
    int gl   = lane & 7;
    int gb   = lane & 24;
    int row  = gwarp * 4 + (lane >> 3);
    if (row >= NTOT) return;

    int s = g_rowptr[row];
    int len = g_rowptr[row + 1] - s;
    int ml = max(len, __shfl_xor_sync(0xffffffffu, len, 8));
    ml = max(ml, __shfl_xor_sync(0xffffffffu, ml, 16));

    const uint4* x4 = (const uint4*)g_x3;
    float a0 = 0.f, a1 = 0.f, a2 = 0.f, a3 = 0.f;
    float a4 = 0.f, a5 = 0.f, a6 = 0.f, a7 = 0.f;
    for (int base = 0; base < ml; base += 8) {
        int i = base + gl;
        int2 myed = (i < len) ? __ldg(&g_edges[s + i]) : make_int2(0, 0);
#pragma unroll
        for (int j = 0; j < 8; j++) {
            int c  = __shfl_sync(0xffffffffu, myed.x, gb + j);
            int vb = __shfl_sync(0xffffffffu, myed.y, gb + j);
            float v = __int_as_float(vb);
            uint4 q = __ldg(&x4[c * 8 + gl]);
            float2 f0 = __bfloat1622float2(*(__nv_bfloat162*)&q.x);
            float2 f1 = __bfloat1622float2(*(__nv_bfloat162*)&q.y);
            float2 f2 = __bfloat1622float2(*(__nv_bfloat162*)&q.z);
            float2 f3 = __bfloat1622float2(*(__nv_bfloat162*)&q.w);
            a0 += v * f0.x; a1 += v * f0.y;
            a2 += v * f1.x; a3 += v * f1.y;
            a4 += v * f2.x; a5 += v * f2.y;
            a6 += v * f3.x; a7 += v * f3.y;
        }
    }

    int eidx = row * 16 + gl * 2;
    float4 ea = ((const float4*)g_ego)[eidx];
    float4 eb = ((const float4*)g_ego)[eidx + 1];
    float dot = a0 * ea.x + a1 * ea.y + a2 * ea.z + a3 * ea.w
              + a4 * eb.x + a5 * eb.y + a6 * eb.z + a7 * eb.w;
    float nn  = a0 * a0 + a1 * a1 + a2 * a2 + a3 * a3
              + a4 * a4 + a5 * a5 + a6 * a6 + a7 * a7;
#pragma unroll
    for (int o = 4; o; o >>= 1) {
        dot += __shfl_xor_sync(0xffffffffu, dot, o);
        nn  += __shfl_xor_sync(0xffffffffu, nn,  o);
    }
    float wgt = dot / fmaxf(sqrtf(nn) * g_norm[row], EPS_F);

    int idx = row * 8 + gl;
    uint4 q1 = ((const uint4*)g_x1)[idx];
    uint4 q2 = ((const uint4*)g_x2)[idx];
    uint4 q3 = ((const uint4*)g_x3)[idx];
    float2 p10 = __bfloat1622float2(*(__nv_bfloat162*)&q1.x);
    float2 p11 = __bfloat1622float2(*(__nv_bfloat162*)&q1.y);
    float2 p12 = __bfloat1622float2(*(__nv_bfloat162*)&q1.z);
    float2 p13 = __bfloat1622float2(*(__nv_bfloat162*)&q1.w);
    float2 p20 = __bfloat1622float2(*(__nv_bfloat162*)&q2.x);
    float2 p21 = __bfloat1622float2(*(__nv_bfloat162*)&q2.y);
    float2 p22 = __bfloat1622float2(*(__nv_bfloat162*)&q2.z);
    float2 p23 = __bfloat1622float2(*(__nv_bfloat162*)&q2.w);
    float2 p30 = __bfloat1622float2(*(__nv_bfloat162*)&q3.x);
    float2 p31 = __bfloat1622float2(*(__nv_bfloat162*)&q3.y);
    float2 p32 = __bfloat1622float2(*(__nv_bfloat162*)&q3.z);
    float2 p33 = __bfloat1622float2(*(__nv_bfloat162*)&q3.w);

    float4 ra, rb;
    ra.x = ea.x + p10.x + p20.x + p30.x + wgt * a0;
    ra.y = ea.y + p10.y + p20.y + p30.y + wgt * a1;
    ra.z = ea.z + p11.x + p21.x + p31.x + wgt * a2;
    ra.w = ea.w + p11.y + p21.y + p31.y + wgt * a3;
    rb.x = eb.x + p12.x + p22.x + p32.x + wgt * a4;
    rb.y = eb.y + p12.y + p22.y + p32.y + wgt * a5;
    rb.z = eb.z + p13.x + p23.x + p33.x + wgt * a6;
    rb.w = eb.w + p13.y + p23.y + p33.y + wgt * a7;
    ((float4*)out)[eidx]     = ra;
    ((float4*)out)[eidx + 1] = rb;
}

// ---------------- side stream (created at static-init; never destroyed) ----
namespace {
struct SideStream {
    cudaStream_t s = 0;
    cudaEvent_t fork = 0, join = 0;
    SideStream() {
        if (cudaStreamCreateWithFlags(&s, cudaStreamNonBlocking) != cudaSuccess) s = 0;
        if (cudaEventCreateWithFlags(&fork, cudaEventDisableTiming) != cudaSuccess) fork = 0;
        if (cudaEventCreateWithFlags(&join, cudaEventDisableTiming) != cudaSuccess) join = 0;
        if (!fork || !join) s = 0;
    }
};
SideStream g_ss;
}

// ---------------- launch ----------------
extern "C" void kernel_launch(void* const* d_in, const int* in_sizes, int n_in,
                              void* d_out, int out_size)
{
    const float* user   = (const float*)d_in[0];
    const float* item   = (const float*)d_in[1];
    const float* prompt = (const float*)d_in[2];
    const float* mw     = (const float*)d_in[3];
    const float* mb     = (const float*)d_in[4];
    const int*   rows   = (const int*)d_in[5];
    const int*   cols   = (const int*)d_in[6];
    const float* vals   = (const float*)d_in[7];
    float* out = (float*)d_out;

    void *p16, *p1, *p2, *p3;
    cudaGetSymbolAddress(&p16, g_ego16);
    cudaGetSymbolAddress(&p1,  g_x1);
    cudaGetSymbolAddress(&p2,  g_x2);
    cudaGetSymbolAddress(&p3,  g_x3);
    __nv_bfloat162* ego16 = (__nv_bfloat162*)p16;
    __nv_bfloat162* x1    = (__nv_bfloat162*)p1;
    __nv_bfloat162* x2    = (__nv_bfloat162*)p2;
    __nv_bfloat162* x3    = (__nv_bfloat162*)p3;

    const int SCAN_BLOCKS = (NTOT + 1023) / 1024;   // 147
    cudaStream_t sb = g_ss.s ? g_ss.s : (cudaStream_t)0;
    bool split = (g_ss.s != 0);

    if (split) {
        cudaEventRecord(g_ss.fork, 0);
        cudaStreamWaitEvent(g_ss.s, g_ss.fork, 0);
    }

    // chain A (stream 0): CSR build
    k_zero   <<<(NTOT + 255) / 256, 256>>>();
    k_hist   <<<2048, 256>>>(rows);
    k_scan1  <<<SCAN_BLOCKS, 1024>>>();
    k_scan2  <<<1, 256>>>(SCAN_BLOCKS);
    k_scan3  <<<SCAN_BLOCKS, 1024>>>();
    k_scatter<<<2048, 256>>>(rows, cols, vals);

    // chain B (side stream): ego + norms + bf16 mirror
    k_ego_user<<<(N_USER * 32 + 255) / 256, 256, 0, sb>>>(user, prompt);
    k_item    <<<(N_ITEM + 127) / 128, 256, 0, sb>>>(item, mw, mb);

    if (split) {
        cudaEventRecord(g_ss.join, g_ss.s);
        cudaStreamWaitEvent(0, g_ss.join, 0);
    }

    // 4 propagation layers — four rows per warp, batch-8 edges
    const int LB = (NTOT / 4 * 32 + 255) / 256;   // 4688 blocks
    k_layerA<<<LB, 256>>>(ego16, x1);
    k_layerA<<<LB, 256>>>(x1,    x2);
    k_layerA<<<LB, 256>>>(x2,    x3);
    k_layerB<<<LB, 256>>>(out);
}

// round 9
// speedup vs baseline: 2.2662x; 1.1507x over previous
#include <cuda_runtime.h>
#include <cuda_bf16.h>
#include <mma.h>

using namespace nvcuda;

#define N_USER 100000
#define N_ITEM 50000
#define NTOT   150000
#define EMB    64
#define FEAT   384
#define NNZ    2400000
#define EPS_F  1e-8f

// ---------------- device scratch (static, no allocations) ----------------
__device__ float          g_ego[NTOT * EMB];       // 38.4 MB fp32
__device__ __nv_bfloat162 g_ego16[NTOT * 32];      // 19.2 MB bf16
__device__ __nv_bfloat162 g_x1[NTOT * 32];
__device__ __nv_bfloat162 g_x2[NTOT * 32];
__device__ __nv_bfloat162 g_x3[NTOT * 32];
__device__ float g_norm[NTOT];
__device__ int   g_counts[NTOT];
__device__ int   g_rank[NNZ];                      // per-edge rank within row
__device__ int   g_rowptr[NTOT + 1];
__device__ int2  g_edges[NNZ];
__device__ int   g_bsum[256];

// ---------------- CSR build (frozen R8 path) ----------------
__global__ void k_zero()
{
    int i = blockIdx.x * blockDim.x + threadIdx.x;
    if (i < NTOT) g_counts[i] = 0;
}

__global__ void k_hist(const int* __restrict__ rows)
{
    int stride = gridDim.x * blockDim.x;
    for (int e = blockIdx.x * blockDim.x + threadIdx.x; e < NNZ; e += stride)
        g_rank[e] = atomicAdd(&g_counts[rows[e]], 1);
}

__global__ void k_scan1()
{
    __shared__ int sh[1024];
    int tid = threadIdx.x;
    int gid = blockIdx.x * 1024 + tid;
    int v = (gid < NTOT) ? g_counts[gid] : 0;
    sh[tid] = v;
    __syncthreads();
    for (int o = 1; o < 1024; o <<= 1) {
        int t = (tid >= o) ? sh[tid - o] : 0;
        __syncthreads();
        if (tid >= o) sh[tid] += t;
        __syncthreads();
    }
    if (gid < NTOT) g_rowptr[gid] = sh[tid] - v;
    if (tid == 1023) g_bsum[blockIdx.x] = sh[1023];
}

__global__ void k_scan2(int nb)
{
    __shared__ int sh[256];
    int tid = threadIdx.x;
    int v = (tid < nb) ? g_bsum[tid] : 0;
    sh[tid] = v;
    __syncthreads();
    for (int o = 1; o < 256; o <<= 1) {
        int t = (tid >= o) ? sh[tid - o] : 0;
        __syncthreads();
        if (tid >= o) sh[tid] += t;
        __syncthreads();
    }
    g_bsum[tid] = sh[tid] - v;
}

__global__ void k_scan3()
{
    int gid = blockIdx.x * 1024 + threadIdx.x;
    if (gid < NTOT) g_rowptr[gid] += g_bsum[blockIdx.x];
    if (gid == 0) g_rowptr[NTOT] = NNZ;
}

__global__ void k_scatter(const int* __restrict__ rows,
                          const int* __restrict__ cols,
                          const float* __restrict__ vals)
{
    int stride = gridDim.x * blockDim.x;
    for (int e = blockIdx.x * blockDim.x + threadIdx.x; e < NNZ; e += stride) {
        int r = rows[e];
        int p = g_rowptr[r] + g_rank[e];
        g_edges[p] = make_int2(cols[e], __float_as_int(vals[e]));
    }
}

// ---------------- ego construction (fused norm + bf16) ----------------
__global__ void k_ego_user(const float* __restrict__ user,
                           const float* __restrict__ prompt)
{
    __shared__ float ps[EMB];
    int tid = threadIdx.x;
    if (tid < EMB) {
        float s = 0.f;
#pragma unroll
        for (int p = 0; p < 8; p++) s += prompt[p * EMB + tid];
        ps[tid] = s;
    }
    __syncthreads();
    int warp = (blockIdx.x * blockDim.x + tid) >> 5;
    int lane = tid & 31;
    if (warp >= N_USER) return;
    float2 u = ((const float2*)user)[warp * 32 + lane];
    float2 p2 = *(const float2*)&ps[lane * 2];
    float vx = u.x + p2.x, vy = u.y + p2.y;
    ((float2*)g_ego)[warp * 32 + lane] = make_float2(vx, vy);
    g_ego16[warp * 32 + lane] = __floats2bfloat162_rn(vx, vy);
    float s = vx * vx + vy * vy;
#pragma unroll
    for (int o = 16; o; o >>= 1) s += __shfl_xor_sync(0xffffffffu, s, o);
    if (lane == 0) g_norm[warp] = sqrtf(s);
}

// ---------------- item GEMM: wmma bf16 split-precision -------------------
// C = Ahi*Bhi + Ahi*Blo + Alo*Bhi (fp32 accum), error ~2^-16.
// Block: 256 thr = 8 warps; tile 128M x 64N; warp = 32x32 (2x2 wmma 16x16).
// In-kernel conversion: fp32 global -> hi/lo bf16 smem per 16-wide k-step.
#define A_LD 24
#define B_LD 72
#define C_LD 68
#define SM_AHI 0
#define SM_ALO (SM_AHI + 128 * A_LD * 2)           // 6144
#define SM_BHI (SM_ALO + 128 * A_LD * 2)           // 12288
#define SM_BLO (SM_BHI + 16 * B_LD * 2)            // 14592
#define SM_TOT_STAGE (SM_BLO + 16 * B_LD * 2)      // 16896
#define SM_TOT (128 * C_LD * 4)                    // 34816 (union, > stage)

__global__ __launch_bounds__(256) void k_item(const float* __restrict__ fea,
                                              const float* __restrict__ w,
                                              const float* __restrict__ b)
{
    __shared__ __align__(16) char smem[SM_TOT];
    __nv_bfloat16* sAhi = (__nv_bfloat16*)(smem + SM_AHI);
    __nv_bfloat16* sAlo = (__nv_bfloat16*)(smem + SM_ALO);
    __nv_bfloat16* sBhi = (__nv_bfloat16*)(smem + SM_BHI);
    __nv_bfloat16* sBlo = (__nv_bfloat16*)(smem + SM_BLO);
    float* sC = (float*)smem;

    int tid = threadIdx.x;
    int wid = tid >> 5;
    int wm = wid & 3;          // 0..3 : m subtile (32 rows)
    int wn = wid >> 2;         // 0..1 : n subtile (32 cols)
    int row0 = blockIdx.x * 128;

    wmma::fragment<wmma::accumulator, 16, 16, 16, float> c[2][2];
#pragma unroll
    for (int i = 0; i < 2; i++)
#pragma unroll
        for (int j = 0; j < 2; j++) wmma::fill_fragment(c[i][j], 0.f);

    for (int k0 = 0; k0 < FEAT; k0 += 16) {
        // stage A tile 128x16: 512 float4, 2 per thread
#pragma unroll
        for (int it = 0; it < 2; it++) {
            int f = tid + it * 256;             // 0..511
            int r = f >> 2, c4 = (f & 3) * 4;
            int gr = row0 + r;
            float4 v = (gr < N_ITEM) ? __ldg((const float4*)&fea[gr * FEAT + k0 + c4])
                                     : make_float4(0.f, 0.f, 0.f, 0.f);
            __nv_bfloat162 h0 = __floats2bfloat162_rn(v.x, v.y);
            __nv_bfloat162 h1 = __floats2bfloat162_rn(v.z, v.w);
            float2 hf0 = __bfloat1622float2(h0);
            float2 hf1 = __bfloat1622float2(h1);
            __nv_bfloat162 l0 = __floats2bfloat162_rn(v.x - hf0.x, v.y - hf0.y);
            __nv_bfloat162 l1 = __floats2bfloat162_rn(v.z - hf1.x, v.w - hf1.y);
            *(__nv_bfloat162*)&sAhi[r * A_LD + c4]     = h0;
            *(__nv_bfloat162*)&sAhi[r * A_LD + c4 + 2] = h1;
            *(__nv_bfloat162*)&sAlo[r * A_LD + c4]     = l0;
            *(__nv_bfloat162*)&sAlo[r * A_LD + c4 + 2] = l1;
        }
        // stage B tile 16x64: 256 float4, 1 per thread
        {
            int r = tid >> 4, c4 = (tid & 15) * 4;
            float4 v = __ldg((const float4*)&w[(k0 + r) * EMB + c4]);
            __nv_bfloat162 h0 = __floats2bfloat162_rn(v.x, v.y);
            __nv_bfloat162 h1 = __floats2bfloat162_rn(v.z, v.w);
            float2 hf0 = __bfloat1622float2(h0);
            float2 hf1 = __bfloat1622float2(h1);
            __nv_bfloat162 l0 = __floats2bfloat162_rn(v.x - hf0.x, v.y - hf0.y);
            __nv_bfloat162 l1 = __floats2bfloat162_rn(v.z - hf1.x, v.w - hf1.y);
            *(__nv_bfloat162*)&sBhi[r * B_LD + c4]     = h0;
            *(__nv_bfloat162*)&sBhi[r * B_LD + c4 + 2] = h1;
            *(__nv_bfloat162*)&sBlo[r * B_LD + c4]     = l0;
            *(__nv_bfloat162*)&sBlo[r * B_LD + c4 + 2] = l1;
        }
        __syncthreads();

        wmma::fragment<wmma::matrix_a, 16, 16, 16, __nv_bfloat16, wmma::row_major> ahi[2], alo[2];
        wmma::fragment<wmma::matrix_b, 16, 16, 16, __nv_bfloat16, wmma::row_major> bhi[2], blo[2];
#pragma unroll
        for (int i = 0; i < 2; i++) {
            wmma::load_matrix_sync(ahi[i], sAhi + (wm * 32 + i * 16) * A_LD, A_LD);
            wmma::load_matrix_sync(alo[i], sAlo + (wm * 32 + i * 16) * A_LD, A_LD);
        }
#pragma unroll
        for (int j = 0; j < 2; j++) {
            wmma::load_matrix_sync(bhi[j], sBhi + wn * 32 + j * 16, B_LD);
            wmma::load_matrix_sync(blo[j], sBlo + wn * 32 + j * 16, B_LD);
        }
#pragma unroll
        for (int i = 0; i < 2; i++)
#pragma unroll
            for (int j = 0; j < 2; j++) {
                wmma::mma_sync(c[i][j], ahi[i], bhi[j], c[i][j]);
                wmma::mma_sync(c[i][j], ahi[i], blo[j], c[i][j]);
                wmma::mma_sync(c[i][j], alo[i], bhi[j], c[i][j]);
            }
        __syncthreads();
    }

    // epilogue: frags -> smem C, then tanh/norm/bf16 (R8-proven pattern)
#pragma unroll
    for (int i = 0; i < 2; i++)
#pragma unroll
        for (int j = 0; j < 2; j++)
            wmma::store_matrix_sync(&sC[(wm * 32 + i * 16) * C_LD + wn * 32 + j * 16],
                                    c[i][j], C_LD, wmma::mem_row_major);
    __syncthreads();

    int ty = tid >> 4;      // 0..15 -> rows ty*8..+7
    int tx = tid & 15;      // cols tx*4..+3
#pragma unroll
    for (int r = 0; r < 8; r++) {
        int lr = ty * 8 + r;
        int gr = row0 + lr;
        float c0 = tanhf(sC[lr * C_LD + tx * 4 + 0] + b[tx * 4 + 0]);
        float c1 = tanhf(sC[lr * C_LD + tx * 4 + 1] + b[tx * 4 + 1]);
        float c2 = tanhf(sC[lr * C_LD + tx * 4 + 2] + b[tx * 4 + 2]);
        float c3 = tanhf(sC[lr * C_LD + tx * 4 + 3] + b[tx * 4 + 3]);
        float s = c0 * c0 + c1 * c1 + c2 * c2 + c3 * c3;
#pragma unroll
        for (int o = 1; o < 16; o <<= 1) s += __shfl_xor_sync(0xffffffffu, s, o);
        if (gr < N_ITEM) {
            int row = N_USER + gr;
            *(float4*)&g_ego[row * EMB + tx * 4] = make_float4(c0, c1, c2, c3);
            g_ego16[row * 32 + tx * 2 + 0] = __floats2bfloat162_rn(c0, c1);
            g_ego16[row * 32 + tx * 2 + 1] = __floats2bfloat162_rn(c2, c3);
            if (tx == 0) g_norm[row] = sqrtf(s);
        }
    }
}

// ---------------- fused SpMM + cosine-reweight, 4 rows/warp, batch-8 ------
__global__ __launch_bounds__(256) void k_layerA(const __nv_bfloat162* __restrict__ xin,
                                                __nv_bfloat162* __restrict__ xout)
{
    int gwarp = (blockIdx.x * blockDim.x + threadIdx.x) >> 5;
    int lane = threadIdx.x & 31;
    int gl   = lane & 7;
    int gb   = lane & 24;
    int row  = gwarp * 4 + (lane >> 3);
    if (row >= NTOT) return;

    int s = g_rowptr[row];
    int len = g_rowptr[row + 1] - s;
    int ml = max(len, __shfl_xor_sync(0xffffffffu, len, 8));
    ml = max(ml, __shfl_xor_sync(0xffffffffu, ml, 16));

    const uint4* x4 = (const uint4*)xin;
    float a0 = 0.f, a1 = 0.f, a2 = 0.f, a3 = 0.f;
    float a4 = 0.f, a5 = 0.f, a6 = 0.f, a7 = 0.f;
    for (int base = 0; base < ml; base += 8) {
        int i = base + gl;
        int2 myed = (i < len) ? __ldg(&g_edges[s + i]) : make_int2(0, 0);
#pragma unroll
        for (int j = 0; j < 8; j++) {
            int c  = __shfl_sync(0xffffffffu, myed.x, gb + j);
            int vb = __shfl_sync(0xffffffffu, myed.y, gb + j);
            float v = __int_as_float(vb);
            uint4 q = __ldg(&x4[c * 8 + gl]);
            float2 f0 = __bfloat1622float2(*(__nv_bfloat162*)&q.x);
            float2 f1 = __bfloat1622float2(*(__nv_bfloat162*)&q.y);
            float2 f2 = __bfloat1622float2(*(__nv_bfloat162*)&q.z);
            float2 f3 = __bfloat1622float2(*(__nv_bfloat162*)&q.w);
            a0 += v * f0.x; a1 += v * f0.y;
            a2 += v * f1.x; a3 += v * f1.y;
            a4 += v * f2.x; a5 += v * f2.y;
            a6 += v * f3.x; a7 += v * f3.y;
        }
    }

    uint4 eq = ((const uint4*)g_ego16)[row * 8 + gl];
    float2 e0 = __bfloat1622float2(*(__nv_bfloat162*)&eq.x);
    float2 e1 = __bfloat1622float2(*(__nv_bfloat162*)&eq.y);
    float2 e2 = __bfloat1622float2(*(__nv_bfloat162*)&eq.z);
    float2 e3 = __bfloat1622float2(*(__nv_bfloat162*)&eq.w);
    float dot = a0 * e0.x + a1 * e0.y + a2 * e1.x + a3 * e1.y
              + a4 * e2.x + a5 * e2.y + a6 * e3.x + a7 * e3.y;
    float nn  = a0 * a0 + a1 * a1 + a2 * a2 + a3 * a3
              + a4 * a4 + a5 * a5 + a6 * a6 + a7 * a7;
#pragma unroll
    for (int o = 4; o; o >>= 1) {
        dot += __shfl_xor_sync(0xffffffffu, dot, o);
        nn  += __shfl_xor_sync(0xffffffffu, nn,  o);
    }
    float wgt = dot / fmaxf(sqrtf(nn) * g_norm[row], EPS_F);

    uint4 oq;
    *(__nv_bfloat162*)&oq.x = __floats2bfloat162_rn(wgt * a0, wgt * a1);
    *(__nv_bfloat162*)&oq.y = __floats2bfloat162_rn(wgt * a2, wgt * a3);
    *(__nv_bfloat162*)&oq.z = __floats2bfloat162_rn(wgt * a4, wgt * a5);
    *(__nv_bfloat162*)&oq.w = __floats2bfloat162_rn(wgt * a6, wgt * a7);
    ((uint4*)xout)[row * 8 + gl] = oq;
}

// final layer: SpMM + reweight + fused total sum  out = ego + x1 + x2 + x3 + x4
__global__ __launch_bounds__(256) void k_layerB(float* __restrict__ out)
{
    int gwarp = (blockIdx.x * blockDim.x + threadIdx.x) >> 5;
    int lane = threadIdx.x & 31;
    int gl   = lane & 7;
    int gb   = lane & 24;
    int row  = gwarp * 4 + (lane >> 3);
    if (row >= NTOT) return;

    int s = g_rowptr[row];
    int len = g_rowptr[row + 1] - s;
    int ml = max(len, __shfl_xor_sync(0xffffffffu, len, 8));
    ml = max(ml, __shfl_xor_sync(0xffffffffu, ml, 16));

    const uint4* x4 = (const uint4*)g_x3;
    float a0 = 0.f, a1 = 0.f, a2 = 0.f, a3 = 0.f;
    float a4 = 0.f, a5 = 0.f, a6 = 0.f, a7 = 0.f;
    for (int base = 0; base < ml; base += 8) {
        int i = base + gl;
        int2 myed = (i < len) ? __ldg(&g_edges[s + i]) : make_int2(0, 0);
#pragma unroll
        for (int j = 0; j < 8; j++) {
            int c  = __shfl_sync(0xffffffffu, myed.x, gb + j);
            int vb = __shfl_sync(0xffffffffu, myed.y, gb + j);
            float v = __int_as_float(vb);
            uint4 q = __ldg(&x4[c * 8 + gl]);
            float2 f0 = __bfloat1622float2(*(__nv_bfloat162*)&q.x);
            float2 f1 = __bfloat1622float2(*(__nv_bfloat162*)&q.y);
            float2 f2 = __bfloat1622float2(*(__nv_bfloat162*)&q.z);
            float2 f3 = __bfloat1622float2(*(__nv_bfloat162*)&q.w);
            a0 += v * f0.x; a1 += v * f0.y;
            a2 += v * f1.x; a3 += v * f1.y;
            a4 += v * f2.x; a5 += v * f2.y;
            a6 += v * f3.x; a7 += v * f3.y;
        }
    }

    int eidx = row * 16 + gl * 2;
    float4 ea = ((const float4*)g_ego)[eidx];
    float4 eb = ((const float4*)g_ego)[eidx + 1];
    float dot = a0 * ea.x + a1 * ea.y + a2 * ea.z + a3 * ea.w
              + a4 * eb.x + a5 * eb.y + a6 * eb.z + a7 * eb.w;
    float nn  = a0 * a0 + a1 * a1 + a2 * a2 + a3 * a3
              + a4 * a4 + a5 * a5 + a6 * a6 + a7 * a7;
#pragma unroll
    for (int o = 4; o; o >>= 1) {
        dot += __shfl_xor_sync(0xffffffffu, dot, o);
        nn  += __shfl_xor_sync(0xffffffffu, nn,  o);
    }
    float wgt = dot / fmaxf(sqrtf(nn) * g_norm[row], EPS_F);

    int idx = row * 8 + gl;
    uint4 q1 = ((const uint4*)g_x1)[idx];
    uint4 q2 = ((const uint4*)g_x2)[idx];
    uint4 q3 = ((const uint4*)g_x3)[idx];
    float2 p10 = __bfloat1622float2(*(__nv_bfloat162*)&q1.x);
    float2 p11 = __bfloat1622float2(*(__nv_bfloat162*)&q1.y);
    float2 p12 = __bfloat1622float2(*(__nv_bfloat162*)&q1.z);
    float2 p13 = __bfloat1622float2(*(__nv_bfloat162*)&q1.w);
    float2 p20 = __bfloat1622float2(*(__nv_bfloat162*)&q2.x);
    float2 p21 = __bfloat1622float2(*(__nv_bfloat162*)&q2.y);
    float2 p22 = __bfloat1622float2(*(__nv_bfloat162*)&q2.z);
    float2 p23 = __bfloat1622float2(*(__nv_bfloat162*)&q2.w);
    float2 p30 = __bfloat1622float2(*(__nv_bfloat162*)&q3.x);
    float2 p31 = __bfloat1622float2(*(__nv_bfloat162*)&q3.y);
    float2 p32 = __bfloat1622float2(*(__nv_bfloat162*)&q3.z);
    float2 p33 = __bfloat1622float2(*(__nv_bfloat162*)&q3.w);

    float4 ra, rb;
    ra.x = ea.x + p10.x + p20.x + p30.x + wgt * a0;
    ra.y = ea.y + p10.y + p20.y + p30.y + wgt * a1;
    ra.z = ea.z + p11.x + p21.x + p31.x + wgt * a2;
    ra.w = ea.w + p11.y + p21.y + p31.y + wgt * a3;
    rb.x = eb.x + p12.x + p22.x + p32.x + wgt * a4;
    rb.y = eb.y + p12.y + p22.y + p32.y + wgt * a5;
    rb.z = eb.z + p13.x + p23.x + p33.x + wgt * a6;
    rb.w = eb.w + p13.y + p23.y + p33.y + wgt * a7;
    ((float4*)out)[eidx]     = ra;
    ((float4*)out)[eidx + 1] = rb;
}

// ---------------- side stream (created at static-init; never destroyed) ----
namespace {
struct SideStream {
    cudaStream_t s = 0;
    cudaEvent_t fork = 0, join = 0;
    SideStream() {
        if (cudaStreamCreateWithFlags(&s, cudaStreamNonBlocking) != cudaSuccess) s = 0;
        if (cudaEventCreateWithFlags(&fork, cudaEventDisableTiming) != cudaSuccess) fork = 0;
        if (cudaEventCreateWithFlags(&join, cudaEventDisableTiming) != cudaSuccess) join = 0;
        if (!fork || !join) s = 0;
    }
};
SideStream g_ss;
}

// ---------------- launch ----------------
extern "C" void kernel_launch(void* const* d_in, const int* in_sizes, int n_in,
                              void* d_out, int out_size)
{
    const float* user   = (const float*)d_in[0];
    const float* item   = (const float*)d_in[1];
    const float* prompt = (const float*)d_in[2];
    const float* mw     = (const float*)d_in[3];
    const float* mb     = (const float*)d_in[4];
    const int*   rows   = (const int*)d_in[5];
    const int*   cols   = (const int*)d_in[6];
    const float* vals   = (const float*)d_in[7];
    float* out = (float*)d_out;

    void *p16, *p1, *p2, *p3;
    cudaGetSymbolAddress(&p16, g_ego16);
    cudaGetSymbolAddress(&p1,  g_x1);
    cudaGetSymbolAddress(&p2,  g_x2);
    cudaGetSymbolAddress(&p3,  g_x3);
    __nv_bfloat162* ego16 = (__nv_bfloat162*)p16;
    __nv_bfloat162* x1    = (__nv_bfloat162*)p1;
    __nv_bfloat162* x2    = (__nv_bfloat162*)p2;
    __nv_bfloat162* x3    = (__nv_bfloat162*)p3;

    const int SCAN_BLOCKS = (NTOT + 1023) / 1024;   // 147
    cudaStream_t sb = g_ss.s ? g_ss.s : (cudaStream_t)0;
    bool split = (g_ss.s != 0);

    if (split) {
        cudaEventRecord(g_ss.fork, 0);
        cudaStreamWaitEvent(g_ss.s, g_ss.fork, 0);
    }

    // chain A (stream 0): CSR build
    k_zero   <<<(NTOT + 255) / 256, 256>>>();
    k_hist   <<<2048, 256>>>(rows);
    k_scan1  <<<SCAN_BLOCKS, 1024>>>();
    k_scan2  <<<1, 256>>>(SCAN_BLOCKS);
    k_scan3  <<<SCAN_BLOCKS, 1024>>>();
    k_scatter<<<2048, 256>>>(rows, cols, vals);

    // chain B (side stream): ego + norms + bf16 mirror
    k_ego_user<<<(N_USER * 32 + 255) / 256, 256, 0, sb>>>(user, prompt);
    k_item    <<<(N_ITEM + 127) / 128, 256, 0, sb>>>(item, mw, mb);

    if (split) {
        cudaEventRecord(g_ss.join, g_ss.s);
        cudaStreamWaitEvent(0, g_ss.join, 0);
    }

    // 4 propagation layers — four rows per warp, batch-8 edges
    const int LB = (NTOT / 4 * 32 + 255) / 256;   // 4688 blocks
    k_layerA<<<LB, 256>>>(ego16, x1);
    k_layerA<<<LB, 256>>>(x1,    x2);
    k_layerA<<<LB, 256>>>(x2,    x3);
    k_layerB<<<LB, 256>>>(out);
}